// round 12
// baseline (speedup 1.0000x reference)
#include <cuda_runtime.h>
#include <math.h>
#include <stdint.h>

// FACT: frame log-softmax + verb/noun gather argmax -> segmentation ->
// segment-mean log-softmax -> combined gather output.
//
// out[t][a] = (vlogF[t]+vlogS[seg(t)])[vid_a] + (nlogF[t]+nlogS[seg(t)])[nid_a]

#define NC1 97
#define NC2 300
#define NCL 397           // NC1 + NC2
#define HID_TOTAL 909     // 512 + 97 + 300
#define TMAX 24000
#define AMAX 4096
#define FPB 4             // frames per block in output kernel

// ---------------- device scratch (no allocations allowed) ----------------
__device__ float g_clogF[TMAX * NCL];     // per-frame [vlog | nlog]
__device__ float g_segC [TMAX * NCL];     // per-segment [vlog | nlog]
__device__ int   g_pred[TMAX];
__device__ int   g_segid[TMAX];
__device__ int   g_segstart[TMAX + 1];
__device__ int   g_numseg;
__device__ int   g_pko[AMAX];             // original order: vid | (97+nid)<<16
__device__ int   g_pks[AMAX];             // vid-sorted: vid | (97+nid)<<7 | orig<<16

// ---------------- setup: pack indices + counting-sort by vid -------------
__global__ void k_setup(const int* __restrict__ vids,
                        const int* __restrict__ nids, int A) {
    __shared__ int cnt[NC1];
    __shared__ int offs[NC1 + 1];
    const int tid = threadIdx.x;
    if (tid < NC1) cnt[tid] = 0;
    __syncthreads();
    for (int a = tid; a < A; a += blockDim.x) {
        int v = vids[a], n = nids[a];
        g_pko[a] = v | ((NC1 + n) << 16);
        atomicAdd(&cnt[v], 1);
    }
    __syncthreads();
    if (tid == 0) {
        int s = 0;
        for (int v = 0; v < NC1; v++) { offs[v] = s; s += cnt[v]; }
        offs[NC1] = s;
    }
    __syncthreads();
    for (int a = tid; a < A; a += blockDim.x) {
        int v = vids[a], n = nids[a];
        int p = atomicAdd(&offs[v], 1);
        g_pks[p] = v | ((NC1 + n) << 7) | (a << 16);
    }
}

// ---------------- K1: per-frame log-softmax + argmax(pred) ---------------
__global__ __launch_bounds__(256) void k_frame(const float* __restrict__ ff,
                                               int T, int A) {
    const int t = blockIdx.x;
    const int tid = threadIdx.x;
    __shared__ float sl[NCL];
    __shared__ unsigned long long rk[256];   // also aliased as 2x float[256]
    float* r0 = (float*)rk;
    float* r1 = r0 + 256;

    const float* row = ff + (size_t)t * HID_TOTAL + (HID_TOTAL - NCL);
    if (tid < NCL)        sl[tid]       = row[tid];
    if (tid + 256 < NCL)  sl[tid + 256] = row[tid + 256];
    __syncthreads();

    // maxima over verb [0,97) and noun [97,397)
    float vm = -INFINITY, nm = -INFINITY;
    for (int c = tid; c < NCL; c += 256) {
        float v = sl[c];
        if (c < NC1) vm = fmaxf(vm, v); else nm = fmaxf(nm, v);
    }
    r0[tid] = vm; r1[tid] = nm; __syncthreads();
    for (int o = 128; o; o >>= 1) {
        if (tid < o) {
            r0[tid] = fmaxf(r0[tid], r0[tid + o]);
            r1[tid] = fmaxf(r1[tid], r1[tid + o]);
        }
        __syncthreads();
    }
    const float vmax = r0[0], nmax = r1[0];
    __syncthreads();

    // exp sums
    float vs = 0.f, ns = 0.f;
    for (int c = tid; c < NCL; c += 256) {
        float v = sl[c];
        if (c < NC1) vs += expf(v - vmax); else ns += expf(v - nmax);
    }
    r0[tid] = vs; r1[tid] = ns; __syncthreads();
    for (int o = 128; o; o >>= 1) {
        if (tid < o) { r0[tid] += r0[tid + o]; r1[tid] += r1[tid + o]; }
        __syncthreads();
    }
    const float cv = vmax + logf(r0[0]);
    const float cn = nmax + logf(r1[0]);
    __syncthreads();   // protect r0/r1 reads before rk reuse

    // write log-softmax table (smem + global)
    float* gout = g_clogF + (size_t)t * NCL;
    for (int c = tid; c < NCL; c += 256) {
        float y = sl[c] - (c < NC1 ? cv : cn);
        sl[c] = y;
        gout[c] = y;
    }
    __syncthreads();

    // argmax over actions (vid-sorted so vid gather broadcasts).
    // 64-bit key: orderable(score) in high bits, (0xFFFF - orig) low bits
    // => ties resolved to smallest original index (matches jnp.argmax).
    unsigned long long best = 0ull;
    for (int a = tid; a < A; a += 256) {
        int pk = g_pks[a];
        float s = sl[pk & 127] + sl[(pk >> 7) & 511];
        unsigned u = __float_as_uint(s);
        u = (u & 0x80000000u) ? ~u : (u | 0x80000000u);
        unsigned long long key =
            (((unsigned long long)u) << 16) | (unsigned)(0xFFFFu - (pk >> 16));
        if (key > best) best = key;
    }
    rk[tid] = best; __syncthreads();
    for (int o = 128; o; o >>= 1) {
        if (tid < o) {
            unsigned long long b = rk[tid + o];
            if (b > rk[tid]) rk[tid] = b;
        }
        __syncthreads();
    }
    if (tid == 0) g_pred[t] = 0xFFFF - (int)(rk[0] & 0xFFFFu);
}

// ---------------- K2: single-block scan -> seg_id + segment starts -------
__global__ __launch_bounds__(1024) void k_scan(int T) {
    const int tid = threadIdx.x;
    __shared__ int s[1024];
    const int chunk = (T + 1023) >> 10;
    const int base = tid * chunk;

    int cnt = 0;
    for (int j = 0; j < chunk; j++) {
        int t = base + j;
        if (t > 0 && t < T) cnt += (g_pred[t] != g_pred[t - 1]);
    }
    s[tid] = cnt; __syncthreads();
    for (int o = 1; o < 1024; o <<= 1) {      // Hillis-Steele inclusive scan
        int v = s[tid];
        if (tid >= o) v += s[tid - o];
        __syncthreads();
        s[tid] = v;
        __syncthreads();
    }
    int run = s[tid] - cnt;                   // exclusive prefix
    for (int j = 0; j < chunk; j++) {
        int t = base + j;
        if (t >= T) break;
        int ch = (t > 0) ? (g_pred[t] != g_pred[t - 1]) : 0;
        run += ch;
        g_segid[t] = run;
        if (ch) g_segstart[run] = t;
        if (t == 0) g_segstart[0] = 0;
        if (t == T - 1) { g_numseg = run + 1; g_segstart[run + 1] = T; }
    }
}

// ---------------- K3: per-segment mean + log-softmax ---------------------
__global__ __launch_bounds__(128) void k_seg(const float* __restrict__ ff,
                                             int T) {
    const int sg = blockIdx.x;
    if (sg >= g_numseg) return;
    const int st = g_segstart[sg], en = g_segstart[sg + 1];
    const float cntf = (float)(en - st);
    const int tid = threadIdx.x;
    __shared__ float m[NCL];
    __shared__ float r0s[128], r1s[128];

    for (int c = tid; c < NCL; c += 128) {
        float acc = 0.f;
        const float* p = ff + (size_t)st * HID_TOTAL + (HID_TOTAL - NCL) + c;
        for (int r = st; r < en; r++) { acc += *p; p += HID_TOTAL; }
        m[c] = acc / cntf;
    }
    __syncthreads();

    float vm = -INFINITY, nm = -INFINITY;
    for (int c = tid; c < NCL; c += 128) {
        float v = m[c];
        if (c < NC1) vm = fmaxf(vm, v); else nm = fmaxf(nm, v);
    }
    r0s[tid] = vm; r1s[tid] = nm; __syncthreads();
    for (int o = 64; o; o >>= 1) {
        if (tid < o) {
            r0s[tid] = fmaxf(r0s[tid], r0s[tid + o]);
            r1s[tid] = fmaxf(r1s[tid], r1s[tid + o]);
        }
        __syncthreads();
    }
    const float vmax = r0s[0], nmax = r1s[0];
    __syncthreads();

    float vs = 0.f, ns = 0.f;
    for (int c = tid; c < NCL; c += 128) {
        float v = m[c];
        if (c < NC1) vs += expf(v - vmax); else ns += expf(v - nmax);
    }
    r0s[tid] = vs; r1s[tid] = ns; __syncthreads();
    for (int o = 64; o; o >>= 1) {
        if (tid < o) { r0s[tid] += r0s[tid + o]; r1s[tid] += r1s[tid + o]; }
        __syncthreads();
    }
    const float cv = vmax + logf(r0s[0]);
    const float cn = nmax + logf(r1s[0]);
    float* gout = g_segC + (size_t)sg * NCL;
    for (int c = tid; c < NCL; c += 128)
        gout[c] = m[c] - (c < NC1 ? cv : cn);
}

// ---------------- K4: combined gather-add output --------------------------
__global__ __launch_bounds__(256) void k_out(float* __restrict__ out,
                                             int T, int A) {
    const int t0 = blockIdx.x * FPB;
    const int tid = threadIdx.x;
    __shared__ float cb[FPB][NCL + 3];   // stride 400 words

    #pragma unroll
    for (int f = 0; f < FPB; f++) {
        int t = t0 + f;
        if (t < T) {
            int sg = g_segid[t];
            const float* a = g_clogF + (size_t)t * NCL;
            const float* b = g_segC + (size_t)sg * NCL;
            for (int c = tid; c < NCL; c += 256) cb[f][c] = a[c] + b[c];
        }
    }
    __syncthreads();

    const int nfull = (t0 + FPB <= T) ? FPB : (T - t0);
    for (int a = tid; a < A; a += 256) {
        int pk = __ldg(&g_pko[a]);
        int iv = pk & 0xFFFF;
        int in2 = pk >> 16;
        #pragma unroll
        for (int f = 0; f < FPB; f++) {
            if (f < nfull)
                out[(size_t)(t0 + f) * A + a] = cb[f][iv] + cb[f][in2];
        }
    }
}

// ---------------- launch ---------------------------------------------------
extern "C" void kernel_launch(void* const* d_in, const int* in_sizes, int n_in,
                              void* d_out, int out_size) {
    const float* ff   = (const float*)d_in[0];   // (T, 1, 909) fp32
    const int*   vids = (const int*)d_in[1];     // (A,) int32
    const int*   nids = (const int*)d_in[2];     // (A,) int32
    const int A = in_sizes[1];
    const int T = in_sizes[0] / HID_TOTAL;
    float* out = (float*)d_out;

    k_setup<<<1, 256>>>(vids, nids, A);
    k_frame<<<T, 256>>>(ff, T, A);
    k_scan<<<1, 1024>>>(T);
    k_seg<<<T, 128>>>(ff, T);
    k_out<<<(T + FPB - 1) / FPB, 256>>>(out, T, A);
}